// round 17
// baseline (speedup 1.0000x reference)
#include <cuda_runtime.h>
#include <cuda_fp16.h>
#include <math_constants.h>
#include <stdint.h>

#define N_NODES  100000
#define N_EDGES  1600000
#define D        64
#define N_GRAPHS 64
#define NBLK     ((N_NODES + 1023) / 1024)   // 98 scan blocks
#define NHALF    50048                        // chunk boundary (multiple of 128)

// ---------------- device scratch (no allocations allowed) ------------------
__device__ float   g_agg[N_NODES * D];    // neighbor means (fp32)
__device__ float   g_h[N_NODES * D];      // layer-0 partial/activations (fp32)
__device__ __half2 g_x16[N_NODES * 32];   // fp16 copy of x (gather operand)
__device__ __half2 g_h16[N_NODES * 32];   // fp16 copy of h (gather operand)
__device__ int     g_cnt[N_NODES];        // histogram (zero-restored each run)
__device__ int     g_off[N_NODES + 1];    // CSR offsets
__device__ int     g_esrc[N_EDGES];       // src ids grouped by dst
__device__ int     g_rank[N_EDGES];       // per-edge rank within its dst
__device__ volatile int g_desc[NBLK];     // scan aggregate descriptors
__device__ uint2   g_Wp[4 * 64 * D];      // pre-split (hi,lo) tf32: W0s,W0n,W1s,W1n

#define CVT_ITEMS (N_NODES * D / 8)
#define HIST_ITEMS (N_EDGES / 4)
#define SCAN_FLAG 0x40000000

// ---------------------------------------------------------------------------
__device__ __forceinline__ void split_tf32(float x, uint32_t& hi, uint32_t& lo) {
    asm("cvt.rna.tf32.f32 %0, %1;" : "=r"(hi) : "f"(x));
    float l = x - __uint_as_float(hi);
    asm("cvt.rna.tf32.f32 %0, %1;" : "=r"(lo) : "f"(l));
}

// pre-split all four weight matrices into (hi,lo) tf32 pairs
__global__ void k_wsplit(const float* __restrict__ W0s, const float* __restrict__ W0n,
                         const float* __restrict__ W1s, const float* __restrict__ W1n) {
    int idx = blockIdx.x * blockDim.x + threadIdx.x;   // 4 * 64 * 64 = 16384
    if (idx >= 4 * 64 * D) return;
    int which = idx >> 12;
    int r = idx & 4095;
    const float* srcs[4] = {W0s, W0n, W1s, W1n};
    uint2 p;
    split_tf32(__ldg(&srcs[which][r]), p.x, p.y);
    g_Wp[idx] = p;
}

__global__ void k_cvt(const float4* __restrict__ in4, uint4* __restrict__ out4) {
    int i = blockIdx.x * blockDim.x + threadIdx.x;
    if (i >= CVT_ITEMS) return;
    float4 v0 = __ldg(&in4[2 * i]);
    float4 v1 = __ldg(&in4[2 * i + 1]);
    uint4 o;
    __half2 h;
    h = __floats2half2_rn(v0.x, v0.y); o.x = *(uint32_t*)&h;
    h = __floats2half2_rn(v0.z, v0.w); o.y = *(uint32_t*)&h;
    h = __floats2half2_rn(v1.x, v1.y); o.z = *(uint32_t*)&h;
    h = __floats2half2_rn(v1.z, v1.w); o.w = *(uint32_t*)&h;
    out4[i] = o;
}

__global__ void k_hist(const int4* __restrict__ dst4, int4* __restrict__ rank4) {
    int i = blockIdx.x * blockDim.x + threadIdx.x;
    if (i < HIST_ITEMS) {
        int4 d = __ldg(&dst4[i]);
        int4 r;
        r.x = atomicAdd(&g_cnt[d.x], 1);
        r.y = atomicAdd(&g_cnt[d.y], 1);
        r.z = atomicAdd(&g_cnt[d.z], 1);
        r.w = atomicAdd(&g_cnt[d.w], 1);
        rank4[i] = r;
    } else if (i < HIST_ITEMS + NBLK) {
        g_desc[i - HIST_ITEMS] = 0;
    }
}

__global__ void __launch_bounds__(1024) k_scan() {
    __shared__ int wsum[32];
    __shared__ int spart[4];
    int t = threadIdx.x, lane = t & 31, wid = t >> 5;
    int b = blockIdx.x;
    int i = b * 1024 + t;
    int c = (i < N_NODES) ? g_cnt[i] : 0;
    int v = c;
#pragma unroll
    for (int o = 1; o < 32; o <<= 1) {
        int u = __shfl_up_sync(0xffffffffu, v, o);
        if (lane >= o) v += u;
    }
    if (lane == 31) wsum[wid] = v;
    __syncthreads();
    if (wid == 0) {
        int w = wsum[lane];
#pragma unroll
        for (int o = 1; o < 32; o <<= 1) {
            int u = __shfl_up_sync(0xffffffffu, w, o);
            if (lane >= o) w += u;
        }
        wsum[lane] = w;
    }
    __syncthreads();
    int base_w = wid ? wsum[wid - 1] : 0;
    int total  = wsum[31];

    if (t == 0) atomicExch((int*)&g_desc[b], total | SCAN_FLAG);

    if (t < 128) {
        int acc = 0;
        if (t < b) {
            int d;
            do { d = g_desc[t]; } while (!(d & SCAN_FLAG));
            acc = d & ~SCAN_FLAG;
        }
#pragma unroll
        for (int o = 16; o >= 1; o >>= 1) acc += __shfl_down_sync(0xffffffffu, acc, o);
        if (lane == 0) spart[wid] = acc;
    }
    __syncthreads();
    int base = spart[0] + spart[1] + spart[2] + spart[3];

    if (i < N_NODES) {
        g_off[i] = base + base_w + v - c;
        g_cnt[i] = 0;
    }
    if (b == 0 && t == 0) g_off[N_NODES] = N_EDGES;
}

__global__ void k_scatter(const int4* __restrict__ src4, const int4* __restrict__ dst4,
                          const int4* __restrict__ rank4) {
    int i = blockIdx.x * blockDim.x + threadIdx.x;
    if (i >= N_EDGES / 4) return;
    int4 d = __ldg(&dst4[i]);
    int4 s = __ldg(&src4[i]);
    int4 r = __ldg(&rank4[i]);
    g_esrc[__ldg(&g_off[d.x]) + r.x] = s.x;
    g_esrc[__ldg(&g_off[d.y]) + r.y] = s.y;
    g_esrc[__ldg(&g_off[d.z]) + r.z] = s.z;
    g_esrc[__ldg(&g_off[d.w]) + r.w] = s.w;
}

// ---------------------------------------------------------------------------
// CSR aggregation over fp16 rows (R11 body) with node-range chunking.
// ---------------------------------------------------------------------------
__device__ __forceinline__ void hacc(float4& a0, float4& a1, int4 r) {
    float2 t;
    t = __half22float2(*(__half2*)&r.x); a0.x += t.x; a0.y += t.y;
    t = __half22float2(*(__half2*)&r.y); a0.z += t.x; a0.w += t.y;
    t = __half22float2(*(__half2*)&r.z); a1.x += t.x; a1.y += t.y;
    t = __half22float2(*(__half2*)&r.w); a1.z += t.x; a1.w += t.y;
}

__global__ void __launch_bounds__(256) k_agg(const int4* __restrict__ feat16,
                                             int nodeBase, int nodeEnd) {
    int lane = threadIdx.x & 31;
    int node = nodeBase + ((blockIdx.x * blockDim.x + threadIdx.x) >> 5);
    if (node >= nodeEnd) return;
    int start = g_off[node];
    int end   = g_off[node + 1];
    int cnt   = end - start;
    int quarter = lane >> 3;
    int q       = lane & 7;

    float4 a0 = make_float4(0.f, 0.f, 0.f, 0.f);
    float4 a1 = a0;

    const int4 z4 = make_int4(0, 0, 0, 0);
    int rounds = (cnt + 15) >> 4;
    int p = start + 4 * quarter;
    for (int it = 0; it < rounds; it++, p += 16) {
        bool v0 = (p     < end);
        bool v1 = (p + 1 < end);
        bool v2 = (p + 2 < end);
        bool v3 = (p + 3 < end);
        int s0 = v0 ? __ldg(&g_esrc[p])     : 0;
        int s1 = v1 ? __ldg(&g_esrc[p + 1]) : 0;
        int s2 = v2 ? __ldg(&g_esrc[p + 2]) : 0;
        int s3 = v3 ? __ldg(&g_esrc[p + 3]) : 0;
        int4 r0 = v0 ? __ldg(&feat16[s0 * 8 + q]) : z4;
        int4 r1 = v1 ? __ldg(&feat16[s1 * 8 + q]) : z4;
        int4 r2 = v2 ? __ldg(&feat16[s2 * 8 + q]) : z4;
        int4 r3 = v3 ? __ldg(&feat16[s3 * 8 + q]) : z4;
        hacc(a0, a1, r0);
        hacc(a0, a1, r1);
        hacc(a0, a1, r2);
        hacc(a0, a1, r3);
    }

    float v[8] = {a0.x, a0.y, a0.z, a0.w, a1.x, a1.y, a1.z, a1.w};
#pragma unroll
    for (int j = 0; j < 8; j++) {
        v[j] += __shfl_xor_sync(0xffffffffu, v[j], 8);
        v[j] += __shfl_xor_sync(0xffffffffu, v[j], 16);
    }
    if (lane < 8) {
        float inv = 1.0f / fmaxf((float)cnt, 1.0f);
        float4 o0 = make_float4(v[0] * inv, v[1] * inv, v[2] * inv, v[3] * inv);
        float4 o1 = make_float4(v[4] * inv, v[5] * inv, v[6] * inv, v[7] * inv);
        *(float4*)&g_agg[node * D + q * 8]     = o0;
        *(float4*)&g_agg[node * D + q * 8 + 4] = o1;
    }
}

// ---------------------------------------------------------------------------
// Split 3xTF32 GEMMs (K=64), W consumed as pre-split (hi,lo) uint2 via __ldg
// (L1-resident, zero split math in the inner loop). Smem holds only A (34.8KB).
// ---------------------------------------------------------------------------
#define TN 128
#define AP2 68
#define GEMM_SMEM (TN * AP2 * (int)sizeof(float))

__device__ __forceinline__ void mma_tf32(float* d, const uint32_t* a,
                                         uint32_t b0, uint32_t b1) {
    asm volatile(
        "mma.sync.aligned.m16n8k8.row.col.f32.tf32.tf32.f32 "
        "{%0,%1,%2,%3}, {%4,%5,%6,%7}, {%8,%9}, {%0,%1,%2,%3};"
        : "+f"(d[0]), "+f"(d[1]), "+f"(d[2]), "+f"(d[3])
        : "r"(a[0]), "r"(a[1]), "r"(a[2]), "r"(a[3]), "r"(b0), "r"(b1));
}

__device__ __forceinline__ void gemm64_core(const float* sIn, const uint2* __restrict__ Wp,
                                            int lane, int mt, float acc[8][4]) {
    int gq = lane >> 2;
    int cq = lane & 3;
    const float* aBase = sIn + (mt * 16 + gq) * AP2 + cq;
    const uint2* bBase = Wp + cq * D + gq;
#pragma unroll 1
    for (int ks = 0; ks < 8; ks++) {
        float a0 = aBase[ks * 8];
        float a1 = aBase[ks * 8 + 8 * AP2];
        float a2 = aBase[ks * 8 + 4];
        float a3 = aBase[ks * 8 + 8 * AP2 + 4];
        uint32_t ah[4], al[4];
        split_tf32(a0, ah[0], al[0]);
        split_tf32(a1, ah[1], al[1]);
        split_tf32(a2, ah[2], al[2]);
        split_tf32(a3, ah[3], al[3]);
        const uint2* bk = bBase + ks * 8 * D;
#pragma unroll
        for (int nt = 0; nt < 8; nt++) {
            uint2 w0 = __ldg(&bk[nt * 8]);           // (hi,lo) row ks*8+cq
            uint2 w1 = __ldg(&bk[4 * D + nt * 8]);   // (hi,lo) row ks*8+cq+4
            mma_tf32(acc[nt], ah, w0.x, w1.x);       // Ah * Bh
            mma_tf32(acc[nt], al, w0.x, w1.x);       // Al * Bh
            mma_tf32(acc[nt], ah, w0.y, w1.y);       // Ah * Bl
        }
    }
}

__global__ void __launch_bounds__(256)
k_gemmS(const float* __restrict__ in, const uint2* __restrict__ Wp,
        float* __restrict__ part) {
    extern __shared__ float smem[];
    float* sIn = smem;
    int tid   = threadIdx.x;
    int node0 = blockIdx.x * TN;

    for (int idx = tid; idx < TN * 16; idx += 256) {
        int n  = idx >> 4;
        int c4 = idx & 15;
        int node = node0 + n;
        float4 v = make_float4(0.f, 0.f, 0.f, 0.f);
        if (node < N_NODES) v = *(const float4*)&in[node * D + 4 * c4];
        *(float4*)&sIn[n * AP2 + 4 * c4] = v;
    }
    __syncthreads();

    int lane = tid & 31, mt = tid >> 5;
    float acc[8][4];
#pragma unroll
    for (int i = 0; i < 8; i++)
#pragma unroll
        for (int j = 0; j < 4; j++) acc[i][j] = 0.f;
    gemm64_core(sIn, Wp, lane, mt, acc);

    int gq = lane >> 2, cq = lane & 3;
    int nodeA = node0 + mt * 16 + gq;
    int nodeB = nodeA + 8;
#pragma unroll
    for (int nt = 0; nt < 8; nt++) {
        int col = nt * 8 + 2 * cq;
        if (nodeA < N_NODES) *(float2*)&part[nodeA * D + col] = make_float2(acc[nt][0], acc[nt][1]);
        if (nodeB < N_NODES) *(float2*)&part[nodeB * D + col] = make_float2(acc[nt][2], acc[nt][3]);
    }
}

template <bool RELU>
__global__ void __launch_bounds__(256)
k_gemmN(const uint2* __restrict__ Wp,
        float* __restrict__ inout,
        __half2* __restrict__ out16,
        int nodeBase, int nodeEnd) {
    extern __shared__ float smem[];
    float* sIn = smem;
    int tid   = threadIdx.x;
    int node0 = nodeBase + blockIdx.x * TN;

    for (int idx = tid; idx < TN * 16; idx += 256) {
        int n  = idx >> 4;
        int c4 = idx & 15;
        int node = node0 + n;
        float4 v = make_float4(0.f, 0.f, 0.f, 0.f);
        if (node < nodeEnd) v = *(const float4*)&g_agg[node * D + 4 * c4];
        *(float4*)&sIn[n * AP2 + 4 * c4] = v;
    }
    __syncthreads();

    int lane = tid & 31, mt = tid >> 5;
    float acc[8][4];
#pragma unroll
    for (int i = 0; i < 8; i++)
#pragma unroll
        for (int j = 0; j < 4; j++) acc[i][j] = 0.f;
    gemm64_core(sIn, Wp, lane, mt, acc);

    int gq = lane >> 2, cq = lane & 3;
    int nodeA = node0 + mt * 16 + gq;
    int nodeB = nodeA + 8;
#pragma unroll
    for (int nt = 0; nt < 8; nt++) {
        int col = nt * 8 + 2 * cq;
        if (nodeA < nodeEnd) {
            float2 pA = *(float2*)&inout[nodeA * D + col];
            float2 oA = make_float2(acc[nt][0] + pA.x, acc[nt][1] + pA.y);
            if (RELU) { oA.x = fmaxf(oA.x, 0.f); oA.y = fmaxf(oA.y, 0.f); }
            *(float2*)&inout[nodeA * D + col] = oA;
            if (RELU) out16[nodeA * 32 + (col >> 1)] = __floats2half2_rn(oA.x, oA.y);
        }
        if (nodeB < nodeEnd) {
            float2 pB = *(float2*)&inout[nodeB * D + col];
            float2 oB = make_float2(acc[nt][2] + pB.x, acc[nt][3] + pB.y);
            if (RELU) { oB.x = fmaxf(oB.x, 0.f); oB.y = fmaxf(oB.y, 0.f); }
            *(float2*)&inout[nodeB * D + col] = oB;
            if (RELU) out16[nodeB * 32 + (col >> 1)] = __floats2half2_rn(oB.x, oB.y);
        }
    }
}

// ---------------------------------------------------------------------------
__device__ __forceinline__ int lower_bound_gid(const int* __restrict__ gid, int key) {
    int lo = 0, hi = N_NODES;
    while (lo < hi) {
        int mid = (lo + hi) >> 1;
        if (__ldg(&gid[mid]) < key) lo = mid + 1;
        else hi = mid;
    }
    return lo;
}

__global__ void __launch_bounds__(512) k_pool(const float4* __restrict__ e4,
                                              const int* __restrict__ gid,
                                              float* __restrict__ fpool) {
    __shared__ float4 sm[32 * 16];
    int g   = blockIdx.x;
    int tid = threadIdx.x;
    int q   = tid & 15;
    int rl  = tid >> 4;

    int lo = lower_bound_gid(gid, g);
    int hi = lower_bound_gid(gid, g + 1);

    float4 m = make_float4(-CUDART_INF_F, -CUDART_INF_F, -CUDART_INF_F, -CUDART_INF_F);
    for (int r = lo + rl; r < hi; r += 32) {
        float4 v = __ldg(&e4[r * 16 + q]);
        m.x = fmaxf(m.x, v.x); m.y = fmaxf(m.y, v.y);
        m.z = fmaxf(m.z, v.z); m.w = fmaxf(m.w, v.w);
    }
    sm[rl * 16 + q] = m;
    __syncthreads();
#pragma unroll
    for (int o = 16; o >= 1; o >>= 1) {
        if (rl < o) {
            float4 a = sm[rl * 16 + q];
            float4 b = sm[(rl + o) * 16 + q];
            a.x = fmaxf(a.x, b.x); a.y = fmaxf(a.y, b.y);
            a.z = fmaxf(a.z, b.z); a.w = fmaxf(a.w, b.w);
            sm[rl * 16 + q] = a;
        }
        __syncthreads();
    }
    if (rl == 0) *(float4*)&fpool[g * D + 4 * q] = sm[q];
}

// ---------------------------------------------------------------------------
extern "C" void kernel_launch(void* const* d_in, const int* in_sizes, int n_in,
                              void* d_out, int out_size) {
    const float* x   = (const float*)d_in[0];
    const int*   src = (const int*)  d_in[1];
    const int*   dst = (const int*)  d_in[2];
    const int*   gid = (const int*)  d_in[3];
    const float* W0s = (const float*)d_in[4];
    const float* W0n = (const float*)d_in[5];
    const float* W1s = (const float*)d_in[6];
    const float* W1n = (const float*)d_in[7];

    float* out = (float*)d_out;
    float* f   = out;                   // [64, 64] pooled
    float* e   = out + N_GRAPHS * D;    // [100000, 64]

    void* p;
    cudaGetSymbolAddress(&p, g_h);    float*   h     = (float*)p;
    cudaGetSymbolAddress(&p, g_rank); int4*    rank4 = (int4*)p;
    cudaGetSymbolAddress(&p, g_x16);  __half2* x16   = (__half2*)p;
    cudaGetSymbolAddress(&p, g_h16);  __half2* h16   = (__half2*)p;
    cudaGetSymbolAddress(&p, g_Wp);   uint2*   Wp    = (uint2*)p;
    uint2* WpS0 = Wp;
    uint2* WpN0 = Wp + 4096;
    uint2* WpS1 = Wp + 8192;
    uint2* WpN1 = Wp + 12288;

    static cudaStream_t s1 = nullptr, s2 = nullptr;
    static cudaEvent_t evRoot, evCvt, evS0, evA0a, evN0a, evH, evS1, evA1a, evN1a;
    if (!s1) {
        cudaStreamCreateWithFlags(&s1, cudaStreamNonBlocking);
        cudaStreamCreateWithFlags(&s2, cudaStreamNonBlocking);
        cudaEventCreateWithFlags(&evRoot, cudaEventDisableTiming);
        cudaEventCreateWithFlags(&evCvt,  cudaEventDisableTiming);
        cudaEventCreateWithFlags(&evS0,   cudaEventDisableTiming);
        cudaEventCreateWithFlags(&evA0a,  cudaEventDisableTiming);
        cudaEventCreateWithFlags(&evN0a,  cudaEventDisableTiming);
        cudaEventCreateWithFlags(&evH,    cudaEventDisableTiming);
        cudaEventCreateWithFlags(&evS1,   cudaEventDisableTiming);
        cudaEventCreateWithFlags(&evA1a,  cudaEventDisableTiming);
        cudaEventCreateWithFlags(&evN1a,  cudaEventDisableTiming);
        cudaFuncSetAttribute(k_gemmS,
                             cudaFuncAttributeMaxDynamicSharedMemorySize, GEMM_SMEM);
        cudaFuncSetAttribute(k_gemmN<true>,
                             cudaFuncAttributeMaxDynamicSharedMemorySize, GEMM_SMEM);
        cudaFuncSetAttribute(k_gemmN<false>,
                             cudaFuncAttributeMaxDynamicSharedMemorySize, GEMM_SMEM);
    }

    const int E4B = (N_EDGES / 4 + 255) / 256;
    const int CVT_B = (CVT_ITEMS + 255) / 256;
    const int HIST_B = (HIST_ITEMS + NBLK + 255) / 256;
    const int GEMM_B  = (N_NODES + TN - 1) / TN;
    const int NB_B = N_NODES - NHALF;
    const int AGG_Ba = NHALF / 8;
    const int AGG_Bb = (NB_B * 32 + 255) / 256;
    const int GEMM_Ba = NHALF / TN;
    const int GEMM_Bb = (NB_B + TN - 1) / TN;

    cudaEventRecord(evRoot, 0);
    cudaStreamWaitEvent(s1, evRoot, 0);
    cudaStreamWaitEvent(s2, evRoot, 0);

    // main: CSR build
    k_hist<<<HIST_B, 256>>>((const int4*)dst, rank4);
    k_scan<<<NBLK, 1024>>>();
    k_scatter<<<E4B, 256>>>((const int4*)src, (const int4*)dst, (const int4*)rank4);

    // s1: W pre-split then layer-0 self gemm; s2: cvt
    k_wsplit<<<(4 * 64 * D + 255) / 256, 256, 0, s1>>>(W0s, W0n, W1s, W1n);
    k_gemmS<<<GEMM_B, 256, GEMM_SMEM, s1>>>(x, WpS0, h);
    cudaEventRecord(evS0, s1);
    k_cvt<<<CVT_B, 256, 0, s2>>>((const float4*)x, (uint4*)x16);
    cudaEventRecord(evCvt, s2);

    // layer 0: chunked agg + neigh-gemm pipeline
    cudaStreamWaitEvent(0, evCvt, 0);
    k_agg<<<AGG_Ba, 256>>>((const int4*)x16, 0, NHALF);
    cudaEventRecord(evA0a, 0);
    k_agg<<<AGG_Bb, 256>>>((const int4*)x16, NHALF, N_NODES);

    cudaStreamWaitEvent(s2, evA0a, 0);
    cudaStreamWaitEvent(s2, evS0, 0);
    k_gemmN<true><<<GEMM_Ba, 256, GEMM_SMEM, s2>>>(WpN0, h, h16, 0, NHALF);
    cudaEventRecord(evN0a, s2);

    cudaStreamWaitEvent(0, evS0, 0);
    k_gemmN<true><<<GEMM_Bb, 256, GEMM_SMEM>>>(WpN0, h, h16, NHALF, N_NODES);
    cudaEventRecord(evH, 0);

    // layer-1 self gemm on s1 (needs full h)
    cudaStreamWaitEvent(s1, evH, 0);
    cudaStreamWaitEvent(s1, evN0a, 0);
    k_gemmS<<<GEMM_B, 256, GEMM_SMEM, s1>>>(h, WpS1, e);
    cudaEventRecord(evS1, s1);

    // layer 1: chunked agg + neigh-gemm (needs full h16 -> wait evN0a)
    cudaStreamWaitEvent(0, evN0a, 0);
    k_agg<<<AGG_Ba, 256>>>((const int4*)h16, 0, NHALF);
    cudaEventRecord(evA1a, 0);
    k_agg<<<AGG_Bb, 256>>>((const int4*)h16, NHALF, N_NODES);

    cudaStreamWaitEvent(s2, evA1a, 0);
    cudaStreamWaitEvent(s2, evS1, 0);
    k_gemmN<false><<<GEMM_Ba, 256, GEMM_SMEM, s2>>>(WpN1, e, nullptr, 0, NHALF);
    cudaEventRecord(evN1a, s2);

    cudaStreamWaitEvent(0, evS1, 0);
    k_gemmN<false><<<GEMM_Bb, 256, GEMM_SMEM>>>(WpN1, e, nullptr, NHALF, N_NODES);

    // pool (needs both chunks of e)
    cudaStreamWaitEvent(0, evN1a, 0);
    k_pool<<<N_GRAPHS, 512>>>((const float4*)e, gid, f);
}